// round 16
// baseline (speedup 1.0000x reference)
#include <cuda_runtime.h>
#include <cuda_bf16.h>

#define NN   50000
#define EE   800000
#define NEG  0.2f

// ---------------- scratch (static device arrays; no allocation allowed) ----
__device__ float g_xl1 [NN*128];
__device__ float g_xr1 [NN*128];
__device__ float g_h1  [NN*128];
__device__ float g_xl2 [NN*128];
__device__ float g_xr2 [NN*128];
__device__ float g_xres[NN*16];
__device__ int   g_deg [NN];
__device__ int   g_rowptr[NN+1];
__device__ int   g_cursor[NN];
__device__ int   g_csr [EE];

// ---------------- CSR build ------------------------------------------------
// edge_index is int32 (JAX x64 disabled): row 0 = src [0..E), row 1 = dst [E..2E)
__global__ void k_count(const int* __restrict__ ei) {
    int e = blockIdx.x*256 + threadIdx.x;
    if (e < EE) {
        unsigned dst = (unsigned)ei[EE + e];
        if (dst < NN) atomicAdd(&g_deg[dst], 1);
    }
}

__global__ void __launch_bounds__(1024) k_scan() {
    __shared__ int s[1024];
    const int tid = threadIdx.x;
    const int per = (NN + 1023) / 1024;          // 49
    int start = tid * per;
    int stop  = min(start + per, NN);
    int sum = 0;
    for (int i = start; i < stop; i++) sum += g_deg[i];
    s[tid] = sum;
    __syncthreads();
    for (int off = 1; off < 1024; off <<= 1) {
        int v = (tid >= off) ? s[tid - off] : 0;
        __syncthreads();
        s[tid] += v;
        __syncthreads();
    }
    int run = s[tid] - sum;                      // exclusive offset for this chunk
    for (int i = start; i < stop; i++) {
        g_rowptr[i] = run;
        g_cursor[i] = run;
        run += g_deg[i];
    }
    // total kept edges = last thread's post-loop running value (inclusive total)
    if (tid == 1023) g_rowptr[NN] = run;
}

__global__ void k_scatter(const int* __restrict__ ei) {
    int e = blockIdx.x*256 + threadIdx.x;
    if (e < EE) {
        unsigned src = (unsigned)ei[e];
        unsigned dst = (unsigned)ei[EE + e];
        if (dst < NN && src < NN) {
            int pos = atomicAdd(&g_cursor[dst], 1);
            g_csr[pos] = (int)src;
        }
    }
}

// ---------------- SIMT GEMM: 128 nodes x <=80 outs per block ----------------
// gridDim.x = node tiles, gridDim.y = out chunks over concat [W0;W1;W2].
// Last chunk may carry up to 80 rows (64 + 16 skip) via the rb loop.
__device__ __forceinline__ void dot4(const float4 a, const float4 b, float& d) {
    d = fmaf(a.x, b.x, d);
    d = fmaf(a.y, b.y, d);
    d = fmaf(a.z, b.z, d);
    d = fmaf(a.w, b.w, d);
}

#define XSTR 132
#define WSTR 132

__global__ void __launch_bounds__(256) k_gemm(
    const float* __restrict__ A,
    const float* __restrict__ W0, const float* __restrict__ B0,
    const float* __restrict__ W1, const float* __restrict__ B1,
    const float* __restrict__ W2,
    float* __restrict__ O0, float* __restrict__ O1, float* __restrict__ O2,
    int outs_total)
{
    extern __shared__ float sm[];
    float* sW = sm;                    // 80*WSTR (max)
    float* sX = sW + 80*WSTR;          // 128*XSTR
    float* sB = sX + 128*XSTR;         // 96

    const int tid = threadIdx.x;
    const int ob  = blockIdx.y * 64;
    const int rows = (blockIdx.y == gridDim.y - 1) ? (outs_total - ob) : 64;  // 64 or 80

    // W chunk -> smem (row stride WSTR floats), per-row source select
    for (int i = tid; i < rows*32; i += 256) {
        int r = i >> 5, q = i & 31;
        int o = ob + r;
        const float4* wr;
        if (o < 128)      wr = (const float4*)(W0 + (size_t)o * 128);
        else if (o < 256) wr = (const float4*)(W1 + (size_t)(o - 128) * 128);
        else              wr = (const float4*)(W2 + (size_t)(o - 256) * 128);
        ((float4*)(sW + r*WSTR))[q] = wr[q];
    }
    if (tid < 96) {
        int o = ob + tid;
        float b = 0.f;
        if (tid < rows) {
            if (o < 128)      b = B0[o];
            else if (o < 256) b = B1[o - 128];
        }
        sB[tid] = b;
    }

    // X tile (128 nodes) -> smem
    const int n0 = blockIdx.x * 128;
    for (int i = tid; i < 4096; i += 256) {
        int r = i >> 5, q = i & 31;
        int n = n0 + r;
        float4 v = make_float4(0.f, 0.f, 0.f, 0.f);
        if (n < NN) v = ((const float4*)(A + (size_t)n * 128))[q];
        ((float4*)(sX + r*XSTR))[q] = v;
    }
    __syncthreads();

    const int tx = tid & 15;          // node lane: nodes tx + 16*i, i=0..7
    const int ty = tid >> 4;          // out group: outs ty*4 .. ty*4+3

    for (int rb = 0; rb < rows; rb += 64) {
        if (rb + ty * 4 >= rows) break;

        float acc[8][4];
        #pragma unroll
        for (int i = 0; i < 8; i++)
            #pragma unroll
            for (int j = 0; j < 4; j++) acc[i][j] = 0.f;

        const float4* wp0 = (const float4*)(sW + (rb + ty*4 + 0) * WSTR);
        const float4* wp1 = (const float4*)(sW + (rb + ty*4 + 1) * WSTR);
        const float4* wp2 = (const float4*)(sW + (rb + ty*4 + 2) * WSTR);
        const float4* wp3 = (const float4*)(sW + (rb + ty*4 + 3) * WSTR);

        #pragma unroll 2
        for (int kq = 0; kq < 32; kq++) {
            float4 wv0 = wp0[kq], wv1 = wp1[kq], wv2 = wp2[kq], wv3 = wp3[kq];
            #pragma unroll
            for (int i = 0; i < 8; i++) {
                float4 xv = ((const float4*)(sX + (tx + 16*i) * XSTR))[kq];
                dot4(xv, wv0, acc[i][0]);
                dot4(xv, wv1, acc[i][1]);
                dot4(xv, wv2, acc[i][2]);
                dot4(xv, wv3, acc[i][3]);
            }
        }

        #pragma unroll
        for (int j = 0; j < 4; j++) {
            int o = ob + rb + ty*4 + j;
            float bv = sB[rb + ty*4 + j];
            #pragma unroll
            for (int i = 0; i < 8; i++) {
                int n = n0 + tx + 16*i;
                if (n >= NN) continue;
                float v = acc[i][j] + bv;
                if (o < 128)      O0[(size_t)n * 128 + o]       = v;
                else if (o < 256) O1[(size_t)n * 128 + (o-128)] = v;
                else              O2[(size_t)n * 16  + (o-256)] = v;
            }
        }
    }
}

// ---------------- warp-per-node attention aggregation -----------------------
// lane = (head h = lane>>2, channel group cg = lane&3 -> channels cg*4..+3).
// One edge = one warp: LDG.128 gather, float4 leaky+dot, 2-SHFL head reduce.
// Self-loop score is the softmax baseline (shift-invariant). Unroll 4 -> 4
// independent gathers + shuffle chains in flight.
__device__ __forceinline__ float grp_sum4(float p) {
    p += __shfl_xor_sync(0xffffffffu, p, 1);
    p += __shfl_xor_sync(0xffffffffu, p, 2);
    return p;
}
__device__ __forceinline__ float4 lrelu4(float4 v) {
    v.x = (v.x > 0.f) ? v.x : NEG * v.x;
    v.y = (v.y > 0.f) ? v.y : NEG * v.y;
    v.z = (v.z > 0.f) ? v.z : NEG * v.z;
    v.w = (v.w > 0.f) ? v.w : NEG * v.w;
    return v;
}
__device__ __forceinline__ float dot4s(const float4 a, const float4 b) {
    return fmaf(a.x, b.x, fmaf(a.y, b.y, fmaf(a.z, b.z, a.w * b.w)));
}

__device__ __forceinline__ void agg_warp_body(
    const float* __restrict__ xlbuf, const float* __restrict__ xrbuf,
    const float* __restrict__ att,
    int d, int lane, float4& acc_out, float& den_out)
{
    const int* __restrict__ csr = g_csr;
    const float4 att4 = *(const float4*)(att   + lane * 4);
    const float4 xr4  = *(const float4*)(xrbuf + (size_t)d * 128 + lane * 4);
    const float4 xs4  = *(const float4*)(xlbuf + (size_t)d * 128 + lane * 4);

    // self-loop -> baseline
    const float m0 = grp_sum4(dot4s(lrelu4(make_float4(
        xs4.x + xr4.x, xs4.y + xr4.y, xs4.z + xr4.z, xs4.w + xr4.w)), att4));
    float den = 1.f;
    float4 acc = xs4;

    const int beg = g_rowptr[d], end = g_rowptr[d + 1];
    int j = beg;
    for (; j + 4 <= end; j += 4) {
        int i0 = csr[j], i1 = csr[j+1], i2 = csr[j+2], i3 = csr[j+3];
        float4 xa = *(const float4*)(xlbuf + (size_t)i0 * 128 + lane * 4);
        float4 xb = *(const float4*)(xlbuf + (size_t)i1 * 128 + lane * 4);
        float4 xc = *(const float4*)(xlbuf + (size_t)i2 * 128 + lane * 4);
        float4 xd = *(const float4*)(xlbuf + (size_t)i3 * 128 + lane * 4);
        float4 ea = lrelu4(make_float4(xa.x + xr4.x, xa.y + xr4.y, xa.z + xr4.z, xa.w + xr4.w));
        float4 eb = lrelu4(make_float4(xb.x + xr4.x, xb.y + xr4.y, xb.z + xr4.z, xb.w + xr4.w));
        float4 ec = lrelu4(make_float4(xc.x + xr4.x, xc.y + xr4.y, xc.z + xr4.z, xc.w + xr4.w));
        float4 ed = lrelu4(make_float4(xd.x + xr4.x, xd.y + xr4.y, xd.z + xr4.z, xd.w + xr4.w));
        float sa = grp_sum4(dot4s(ea, att4));
        float sb = grp_sum4(dot4s(eb, att4));
        float sc = grp_sum4(dot4s(ec, att4));
        float sd = grp_sum4(dot4s(ed, att4));
        float wa = __expf(sa - m0);
        float wb = __expf(sb - m0);
        float wc = __expf(sc - m0);
        float wd = __expf(sd - m0);
        den += (wa + wb) + (wc + wd);
        acc.x = fmaf(wa, xa.x, fmaf(wb, xb.x, fmaf(wc, xc.x, fmaf(wd, xd.x, acc.x))));
        acc.y = fmaf(wa, xa.y, fmaf(wb, xb.y, fmaf(wc, xc.y, fmaf(wd, xd.y, acc.y))));
        acc.z = fmaf(wa, xa.z, fmaf(wb, xb.z, fmaf(wc, xc.z, fmaf(wd, xd.z, acc.z))));
        acc.w = fmaf(wa, xa.w, fmaf(wb, xb.w, fmaf(wc, xc.w, fmaf(wd, xd.w, acc.w))));
    }
    for (; j < end; j++) {
        int ia = csr[j];
        float4 xa = *(const float4*)(xlbuf + (size_t)ia * 128 + lane * 4);
        float4 ea = lrelu4(make_float4(xa.x + xr4.x, xa.y + xr4.y, xa.z + xr4.z, xa.w + xr4.w));
        float sa = grp_sum4(dot4s(ea, att4));
        float wa = __expf(sa - m0);
        den += wa;
        acc.x = fmaf(wa, xa.x, acc.x);
        acc.y = fmaf(wa, xa.y, acc.y);
        acc.z = fmaf(wa, xa.z, acc.z);
        acc.w = fmaf(wa, xa.w, acc.w);
    }
    acc_out = acc; den_out = den;
}

__global__ void __launch_bounds__(256) k_agg1(
    const float* __restrict__ att,  const float* __restrict__ bias,
    const float* __restrict__ bnw,  const float* __restrict__ bnb,
    const float* __restrict__ bnrm, const float* __restrict__ bnrv)
{
    const int warp = threadIdx.x >> 5;
    const int lane = threadIdx.x & 31;
    const int d = blockIdx.x * 8 + warp;
    if (d >= NN) return;

    float4 acc; float den;
    agg_warp_body(g_xl1, g_xr1, att, d, lane, acc, den);

    const float inv = 1.f / den;
    float4 b4  = *(const float4*)(bias + lane * 4);
    float4 w4  = *(const float4*)(bnw  + lane * 4);
    float4 c4  = *(const float4*)(bnb  + lane * 4);
    float4 m4  = *(const float4*)(bnrm + lane * 4);
    float4 v4  = *(const float4*)(bnrv + lane * 4);

    float4 o;
    o.x = (acc.x * inv + b4.x - m4.x) * rsqrtf(v4.x + 1e-5f) * w4.x + c4.x;
    o.y = (acc.y * inv + b4.y - m4.y) * rsqrtf(v4.y + 1e-5f) * w4.y + c4.y;
    o.z = (acc.z * inv + b4.z - m4.z) * rsqrtf(v4.z + 1e-5f) * w4.z + c4.z;
    o.w = (acc.w * inv + b4.w - m4.w) * rsqrtf(v4.w + 1e-5f) * w4.w + c4.w;
    o.x = (o.x > 0.f) ? o.x : (__expf(o.x) - 1.f);
    o.y = (o.y > 0.f) ? o.y : (__expf(o.y) - 1.f);
    o.z = (o.z > 0.f) ? o.z : (__expf(o.z) - 1.f);
    o.w = (o.w > 0.f) ? o.w : (__expf(o.w) - 1.f);

    *(float4*)(g_h1 + (size_t)d * 128 + lane * 4) = o;
}

__global__ void __launch_bounds__(256) k_agg2(
    const float* __restrict__ att, const float* __restrict__ bias2,
    const float* __restrict__ lnw, const float* __restrict__ lnb,
    float* __restrict__ out)
{
    const int warp = threadIdx.x >> 5;
    const int lane = threadIdx.x & 31;
    const int d = blockIdx.x * 8 + warp;
    if (d >= NN) return;

    float4 acc; float den;
    agg_warp_body(g_xl2, g_xr2, att, d, lane, acc, den);

    const float inv = 1.f / den;
    float4 v = make_float4(acc.x * inv, acc.y * inv, acc.z * inv, acc.w * inv);

    // mean over 8 heads: butterfly over lanes differing in bits 2..4
    #pragma unroll
    for (int s = 4; s <= 16; s <<= 1) {
        v.x += __shfl_xor_sync(0xffffffffu, v.x, s);
        v.y += __shfl_xor_sync(0xffffffffu, v.y, s);
        v.z += __shfl_xor_sync(0xffffffffu, v.z, s);
        v.w += __shfl_xor_sync(0xffffffffu, v.w, s);
    }
    const int cg = lane & 3;
    float4 b2 = *(const float4*)(bias2 + cg * 4);
    float4 xr = *(const float4*)(g_xres + (size_t)d * 16 + cg * 4);
    v.x = v.x * 0.125f + b2.x + xr.x;
    v.y = v.y * 0.125f + b2.y + xr.y;
    v.z = v.z * 0.125f + b2.z + xr.z;
    v.w = v.w * 0.125f + b2.w + xr.w;

    // LayerNorm over 16 channels (4 components x 4 cg lanes)
    float mu = (v.x + v.y) + (v.z + v.w);
    mu += __shfl_xor_sync(0xffffffffu, mu, 1);
    mu += __shfl_xor_sync(0xffffffffu, mu, 2);
    mu *= (1.f / 16.f);
    float dx = v.x - mu, dy = v.y - mu, dz = v.z - mu, dw = v.w - mu;
    float var = (dx * dx + dy * dy) + (dz * dz + dw * dw);
    var += __shfl_xor_sync(0xffffffffu, var, 1);
    var += __shfl_xor_sync(0xffffffffu, var, 2);
    var *= (1.f / 16.f);
    float rs = rsqrtf(var + 1e-5f);

    if (lane < 4) {
        float4 lw = *(const float4*)(lnw + cg * 4);
        float4 lb = *(const float4*)(lnb + cg * 4);
        float4 o;
        o.x = dx * rs * lw.x + lb.x;
        o.y = dy * rs * lw.y + lb.y;
        o.z = dz * rs * lw.z + lb.z;
        o.w = dw * rs * lw.w + lb.w;
        *(float4*)(out + (size_t)d * 16 + cg * 4) = o;
    }
}

// ---------------- host ------------------------------------------------------
extern "C" void kernel_launch(void* const* d_in, const int* in_sizes, int n_in,
                              void* d_out, int out_size)
{
    const float* x     = (const float*)d_in[0];
    const int*   ei    = (const int*)d_in[1];      // int32: JAX x64 disabled
    const float* Wl1   = (const float*)d_in[2];
    const float* bl1   = (const float*)d_in[3];
    const float* Wr1   = (const float*)d_in[4];
    const float* br1   = (const float*)d_in[5];
    const float* att1  = (const float*)d_in[6];
    const float* bias1 = (const float*)d_in[7];
    const float* bnw   = (const float*)d_in[8];
    const float* bnb   = (const float*)d_in[9];
    const float* bnrm  = (const float*)d_in[10];
    const float* bnrv  = (const float*)d_in[11];
    const float* Wl2   = (const float*)d_in[12];
    const float* bl2   = (const float*)d_in[13];
    const float* Wr2   = (const float*)d_in[14];
    const float* br2   = (const float*)d_in[15];
    const float* att2  = (const float*)d_in[16];
    const float* bias2 = (const float*)d_in[17];
    const float* Wskip = (const float*)d_in[18];
    const float* lnw   = (const float*)d_in[19];
    const float* lnb   = (const float*)d_in[20];
    float*       out   = (float*)d_out;

    float *xl1, *xr1, *h1, *xl2, *xr2, *xres;
    int* degp;
    cudaGetSymbolAddress((void**)&xl1,  g_xl1);
    cudaGetSymbolAddress((void**)&xr1,  g_xr1);
    cudaGetSymbolAddress((void**)&h1,   g_h1);
    cudaGetSymbolAddress((void**)&xl2,  g_xl2);
    cudaGetSymbolAddress((void**)&xr2,  g_xr2);
    cudaGetSymbolAddress((void**)&xres, g_xres);
    cudaGetSymbolAddress((void**)&degp, g_deg);

    const int smem = (80*WSTR + 128*XSTR + 96) * 4;   // ~110.2 KB -> 2 blocks/SM
    cudaFuncSetAttribute(k_gemm, cudaFuncAttributeMaxDynamicSharedMemorySize, smem);

    // CSR build (recomputed each call; deterministic)
    cudaMemsetAsync(degp, 0, NN * sizeof(int));
    k_count<<<(EE + 255) / 256, 256>>>(ei);
    k_scan<<<1, 1024>>>();
    k_scatter<<<(EE + 255) / 256, 256>>>(ei);

    const int NTILES = (NN + 127) / 128;   // 391
    const int AGG_GRID = (NN + 7) / 8;     // 6250

    // conv1 transforms + skip projection (272 outs -> 4 chunks, last = 80 rows)
    k_gemm<<<dim3(NTILES, 4), 256, smem>>>(x, Wl1, bl1, Wr1, br1, Wskip,
                                           xl1, xr1, xres, 272);
    // conv1 aggregation + BN + ELU
    k_agg1<<<AGG_GRID, 256>>>(att1, bias1, bnw, bnb, bnrm, bnrv);

    // conv2 transforms (256 outs -> 4 chunks of 64)
    k_gemm<<<dim3(NTILES, 4), 256, smem>>>(h1, Wl2, bl2, Wr2, br2, nullptr,
                                           xl2, xr2, nullptr, 256);
    // conv2 aggregation + head-mean + skip + LayerNorm
    k_agg2<<<AGG_GRID, 256>>>(att2, bias2, lnw, lnb, out);
}